// round 7
// baseline (speedup 1.0000x reference)
#include <cuda_runtime.h>
#include <math.h>

// CPn lattice action, B x 64x64 lattice, n=6 angles/site -> z in C^4.
// ONE 256-thread CTA per batch: 8 warps x 8 rows, lane owns a column pair
// packed as f32x2. Row-neighbor via sequential row iteration; warp-boundary
// rows exchanged via smem (incl. the 63->0 wrap, zero halo recompute).
// Col-neighbor via 1 SHFL per component. Direct out[b] store.
// launch_bounds(256,5): <=51 regs -> 40 warps/SM occupancy cap.
// Trig identities: sin(mod(a,pi)) = |sin a|, cos(mod(a,pi)) = cos(a)*sign(sin a),
// mod 2pi is a no-op under sin/cos.

#define LSZ 64
#define SITES (LSZ * LSZ)      // 4096
#define NCH 6
#define RPW 8                  // rows per warp
#define NWARPS 8               // 8 warps -> 64 rows = whole batch
#define NTHREADS (NWARPS * 32) // 256

typedef unsigned long long u64;

__device__ __forceinline__ u64 pk2(float x, float y) {
    u64 r; asm("mov.b64 %0, {%1,%2};" : "=l"(r) : "f"(x), "f"(y)); return r;
}
__device__ __forceinline__ void upk2(u64 v, float& x, float& y) {
    asm("mov.b64 {%0,%1}, %2;" : "=f"(x), "=f"(y) : "l"(v));
}
__device__ __forceinline__ u64 fma2(u64 a, u64 b, u64 c) {
    u64 d; asm("fma.rn.f32x2 %0, %1, %2, %3;" : "=l"(d) : "l"(a), "l"(b), "l"(c)); return d;
}
__device__ __forceinline__ u64 mul2(u64 a, u64 b) {
    u64 d; asm("mul.rn.f32x2 %0, %1, %2;" : "=l"(d) : "l"(a), "l"(b)); return d;
}
__device__ __forceinline__ u64 sub2(u64 a, u64 b) {
    u64 d; asm("sub.rn.f32x2 %0, %1, %2;" : "=l"(d) : "l"(a), "l"(b)); return d;
}

// z-vector (7 comps) from 6 angles, no explicit range reduction
__device__ __forceinline__ void site_z(const float a[6], float z[7]) {
    float s[6], c[6];
    #pragma unroll
    for (int k = 0; k < 5; k++) {
        float sa = __sinf(a[k]);
        float ca = __cosf(a[k]);
        s[k] = fabsf(sa);
        c[k] = __uint_as_float(__float_as_uint(ca) ^
                               (__float_as_uint(sa) & 0x80000000u));
    }
    s[5] = __sinf(a[5]);
    c[5] = __cosf(a[5]);
    float sc = s[0];
    z[0] = c[0];
    z[1] = c[1] * sc; sc *= s[1];
    z[2] = c[2] * sc; sc *= s[2];
    z[3] = c[3] * sc; sc *= s[3];
    z[4] = c[4] * sc; sc *= s[4];   // zi0
    z[5] = c[5] * sc; sc *= s[5];   // zi1
    z[6] = sc;                      // zi2 (zi3 == 0 identically)
}

__device__ __forceinline__ void load_row_z(const float4* __restrict__ f4,
                                           int row, int lidx, u64 Z[7]) {
    int base = row * 96 + lidx;                // 96 float4 per row
    float4 v0 = f4[base], v1 = f4[base + 1], v2 = f4[base + 2];
    float aA[6] = {v0.x, v0.y, v0.z, v0.w, v1.x, v1.y};
    float aB[6] = {v1.z, v1.w, v2.x, v2.y, v2.z, v2.w};
    float zA[7], zB[7];
    site_z(aA, zA);
    site_z(aB, zB);
    #pragma unroll
    for (int k = 0; k < 7; k++) Z[k] = pk2(zA[k], zB[k]);
}

// acc += dre^2 + dim^2, packed over 2 sites
__device__ __forceinline__ void accdot(const u64 S[7], const u64 N[7], u64& acc) {
    u64 pos = mul2(S[0], N[0]);
    pos = fma2(S[1], N[1], pos);
    pos = fma2(S[2], N[2], pos);
    pos = fma2(S[3], N[3], pos);
    u64 neg = mul2(S[4], N[4]);
    neg = fma2(S[5], N[5], neg);
    neg = fma2(S[6], N[6], neg);
    u64 dre = sub2(pos, neg);
    u64 dim = mul2(S[0], N[4]);
    dim = fma2(S[1], N[5], dim);
    dim = fma2(S[2], N[6], dim);
    dim = fma2(S[4], N[0], dim);
    dim = fma2(S[5], N[1], dim);
    dim = fma2(S[6], N[2], dim);
    acc = fma2(dre, dre, acc);
    acc = fma2(dim, dim, acc);
}

// column-direction dot: neighbor of pair (2l, 2l+1) is (2l+1, 2l+2)
__device__ __forceinline__ void coldot(const u64 S[7], int lane, u64& acc) {
    u64 C[7];
    #pragma unroll
    for (int k = 0; k < 7; k++) {
        float slo, shi;
        upk2(S[k], slo, shi);
        float nlo = __shfl_sync(0xffffffffu, slo, (lane + 1) & 31);
        C[k] = pk2(shi, nlo);
    }
    accdot(S, C, acc);
}

__global__ void __launch_bounds__(NTHREADS, 5)
cpn_main(const float* __restrict__ phi, float* __restrict__ out)
{
    const int b    = blockIdx.x;
    const int w    = threadIdx.x >> 5;
    const int lane = threadIdx.x & 31;
    const int r0   = w * RPW;                 // first owned row
    const float4* __restrict__ f4 =
        reinterpret_cast<const float4*>(phi + (size_t)b * SITES * NCH);
    const int lidx = 3 * lane;

    __shared__ u64 firstz[NWARPS][7][32];
    __shared__ float red[NWARPS];

    // first owned row -> S, publish for the warp above (row wrap included)
    u64 S[7];
    load_row_z(f4, r0, lidx, S);
    #pragma unroll
    for (int k = 0; k < 7; k++) firstz[w][k][lane] = S[k];
    __syncthreads();

    u64 acc2 = pk2(0.0f, 0.0f);
    #pragma unroll 2
    for (int r = 1; r < RPW; r++) {
        u64 R[7];
        load_row_z(f4, r0 + r, lidx, R);   // loads hoist above coldot math
        coldot(S, lane, acc2);
        accdot(S, R, acc2);                // row-direction
        #pragma unroll
        for (int k = 0; k < 7; k++) S[k] = R[k];
    }

    // boundary: col dot + row dot vs next warp's first row (wraps 63->0)
    coldot(S, lane, acc2);
    {
        u64 N[7];
        int nw = (w + 1) & (NWARPS - 1);
        #pragma unroll
        for (int k = 0; k < 7; k++) N[k] = firstz[nw][k][lane];
        accdot(S, N, acc2);
    }

    // reduce: packed -> scalar -> warp -> block
    float alo, ahi;
    upk2(acc2, alo, ahi);
    float acc = alo + ahi;
    #pragma unroll
    for (int o = 16; o > 0; o >>= 1)
        acc += __shfl_down_sync(0xffffffffu, acc, o);
    if (lane == 0) red[w] = acc;
    __syncthreads();
    if (threadIdx.x == 0) {
        float v = 0.0f;
        #pragma unroll
        for (int i = 0; i < NWARPS; i++) v += red[i];
        // action = -4 * sum(dre^2 + dim^2 - 1), 2 dirs * 4096 sites
        out[b] = -4.0f * (v - 2.0f * (float)SITES);
    }
}

extern "C" void kernel_launch(void* const* d_in, const int* in_sizes, int n_in,
                              void* d_out, int out_size)
{
    const float* phi = (const float*)d_in[0];
    // d_in[1] (shift) is the fixed (+1 row, +1 col) roll; handled analytically.
    int B = in_sizes[0] / (SITES * NCH);
    cpn_main<<<B, NTHREADS>>>(phi, (float*)d_out);
}

// round 8
// speedup vs baseline: 1.1028x; 1.1028x over previous
#include <cuda_runtime.h>
#include <math.h>

// CPn lattice action, B x 64x64 lattice, n=6 angles/site -> z in C^4.
// ONE 512-thread CTA per batch: 16 warps x 4 rows, lane owns a column pair
// packed as f32x2. Row-neighbor via sequential row iteration; warp-boundary
// rows exchanged via smem (incl. the 63->0 wrap, zero halo recompute).
// Col-neighbor via 1 SHFL per component. Direct out[b] store.
// 64 regs/thread natural -> 2 CTAs/SM = 32 warps/SM.
// Trig identities: sin(mod(a,pi)) = |sin a|, cos(mod(a,pi)) = cos(a)*sign(sin a),
// mod 2pi is a no-op under sin/cos.

#define LSZ 64
#define SITES (LSZ * LSZ)      // 4096
#define NCH 6
#define RPW 4                  // rows per warp
#define NWARPS 16              // 16 warps -> 64 rows = whole batch
#define NTHREADS (NWARPS * 32) // 512

typedef unsigned long long u64;

__device__ __forceinline__ u64 pk2(float x, float y) {
    u64 r; asm("mov.b64 %0, {%1,%2};" : "=l"(r) : "f"(x), "f"(y)); return r;
}
__device__ __forceinline__ void upk2(u64 v, float& x, float& y) {
    asm("mov.b64 {%0,%1}, %2;" : "=f"(x), "=f"(y) : "l"(v));
}
__device__ __forceinline__ u64 fma2(u64 a, u64 b, u64 c) {
    u64 d; asm("fma.rn.f32x2 %0, %1, %2, %3;" : "=l"(d) : "l"(a), "l"(b), "l"(c)); return d;
}
__device__ __forceinline__ u64 mul2(u64 a, u64 b) {
    u64 d; asm("mul.rn.f32x2 %0, %1, %2;" : "=l"(d) : "l"(a), "l"(b)); return d;
}
__device__ __forceinline__ u64 sub2(u64 a, u64 b) {
    u64 d; asm("sub.rn.f32x2 %0, %1, %2;" : "=l"(d) : "l"(a), "l"(b)); return d;
}

// z-vector (7 comps) from 6 angles, no explicit range reduction
__device__ __forceinline__ void site_z(const float a[6], float z[7]) {
    float s[6], c[6];
    #pragma unroll
    for (int k = 0; k < 5; k++) {
        float sa = __sinf(a[k]);
        float ca = __cosf(a[k]);
        s[k] = fabsf(sa);
        c[k] = __uint_as_float(__float_as_uint(ca) ^
                               (__float_as_uint(sa) & 0x80000000u));
    }
    s[5] = __sinf(a[5]);
    c[5] = __cosf(a[5]);
    float sc = s[0];
    z[0] = c[0];
    z[1] = c[1] * sc; sc *= s[1];
    z[2] = c[2] * sc; sc *= s[2];
    z[3] = c[3] * sc; sc *= s[3];
    z[4] = c[4] * sc; sc *= s[4];   // zi0
    z[5] = c[5] * sc; sc *= s[5];   // zi1
    z[6] = sc;                      // zi2 (zi3 == 0 identically)
}

__device__ __forceinline__ void load_row_z(const float4* __restrict__ f4,
                                           int row, int lidx, u64 Z[7]) {
    int base = row * 96 + lidx;                // 96 float4 per row
    float4 v0 = f4[base], v1 = f4[base + 1], v2 = f4[base + 2];
    float aA[6] = {v0.x, v0.y, v0.z, v0.w, v1.x, v1.y};
    float aB[6] = {v1.z, v1.w, v2.x, v2.y, v2.z, v2.w};
    float zA[7], zB[7];
    site_z(aA, zA);
    site_z(aB, zB);
    #pragma unroll
    for (int k = 0; k < 7; k++) Z[k] = pk2(zA[k], zB[k]);
}

// acc += dre^2 + dim^2, packed over 2 sites
__device__ __forceinline__ void accdot(const u64 S[7], const u64 N[7], u64& acc) {
    u64 pos = mul2(S[0], N[0]);
    pos = fma2(S[1], N[1], pos);
    pos = fma2(S[2], N[2], pos);
    pos = fma2(S[3], N[3], pos);
    u64 neg = mul2(S[4], N[4]);
    neg = fma2(S[5], N[5], neg);
    neg = fma2(S[6], N[6], neg);
    u64 dre = sub2(pos, neg);
    u64 dim = mul2(S[0], N[4]);
    dim = fma2(S[1], N[5], dim);
    dim = fma2(S[2], N[6], dim);
    dim = fma2(S[4], N[0], dim);
    dim = fma2(S[5], N[1], dim);
    dim = fma2(S[6], N[2], dim);
    acc = fma2(dre, dre, acc);
    acc = fma2(dim, dim, acc);
}

// column-direction dot: neighbor of pair (2l, 2l+1) is (2l+1, 2l+2)
__device__ __forceinline__ void coldot(const u64 S[7], int lane, u64& acc) {
    u64 C[7];
    #pragma unroll
    for (int k = 0; k < 7; k++) {
        float slo, shi;
        upk2(S[k], slo, shi);
        float nlo = __shfl_sync(0xffffffffu, slo, (lane + 1) & 31);
        C[k] = pk2(shi, nlo);
    }
    accdot(S, C, acc);
}

__global__ void __launch_bounds__(NTHREADS, 2)
cpn_main(const float* __restrict__ phi, float* __restrict__ out)
{
    const int b    = blockIdx.x;
    const int w    = threadIdx.x >> 5;
    const int lane = threadIdx.x & 31;
    const int r0   = w * RPW;                 // first owned row
    const float4* __restrict__ f4 =
        reinterpret_cast<const float4*>(phi + (size_t)b * SITES * NCH);
    const int lidx = 3 * lane;

    __shared__ u64 firstz[NWARPS][7][32];
    __shared__ float red[NWARPS];

    // first owned row -> S, publish for the warp above (row wrap included)
    u64 S[7];
    load_row_z(f4, r0, lidx, S);
    #pragma unroll
    for (int k = 0; k < 7; k++) firstz[w][k][lane] = S[k];
    __syncthreads();

    u64 acc2 = pk2(0.0f, 0.0f);
    #pragma unroll
    for (int r = 1; r < RPW; r++) {
        u64 R[7];
        load_row_z(f4, r0 + r, lidx, R);   // loads hoist above coldot math
        coldot(S, lane, acc2);
        accdot(S, R, acc2);                // row-direction
        #pragma unroll
        for (int k = 0; k < 7; k++) S[k] = R[k];
    }

    // boundary: col dot + row dot vs next warp's first row (wraps 63->0)
    coldot(S, lane, acc2);
    {
        u64 N[7];
        int nw = (w + 1) & (NWARPS - 1);
        #pragma unroll
        for (int k = 0; k < 7; k++) N[k] = firstz[nw][k][lane];
        accdot(S, N, acc2);
    }

    // reduce: packed -> scalar -> warp -> block
    float alo, ahi;
    upk2(acc2, alo, ahi);
    float acc = alo + ahi;
    #pragma unroll
    for (int o = 16; o > 0; o >>= 1)
        acc += __shfl_down_sync(0xffffffffu, acc, o);
    if (lane == 0) red[w] = acc;
    __syncthreads();
    if (threadIdx.x == 0) {
        float v = 0.0f;
        #pragma unroll
        for (int i = 0; i < NWARPS; i++) v += red[i];
        // action = -4 * sum(dre^2 + dim^2 - 1), 2 dirs * 4096 sites
        out[b] = -4.0f * (v - 2.0f * (float)SITES);
    }
}

extern "C" void kernel_launch(void* const* d_in, const int* in_sizes, int n_in,
                              void* d_out, int out_size)
{
    const float* phi = (const float*)d_in[0];
    // d_in[1] (shift) is the fixed (+1 row, +1 col) roll; handled analytically.
    int B = in_sizes[0] / (SITES * NCH);
    cpn_main<<<B, NTHREADS>>>(phi, (float*)d_out);
}

// round 11
// speedup vs baseline: 1.1122x; 1.0085x over previous
#include <cuda_runtime.h>
#include <math.h>

// CPn lattice action, B x 64x64 lattice, n=6 angles/site -> z in C^4.
// ONE 256-thread CTA per batch: 8 warps x 8 rows, lane owns a column pair
// packed as f32x2. TWO rows in flight per loop iteration (6 LDG.128 + 4
// independent site_z chains) for per-warp ILP; dual accumulators split the
// dependency chain. Warp-boundary rows exchanged via smem (incl. 63->0 wrap).
// Col-neighbor via 1 SHFL per component. Direct out[b] store.
// Trig identities: sin(mod(a,pi)) = |sin a|, cos(mod(a,pi)) = cos(a)*sign(sin a),
// mod 2pi is a no-op under sin/cos.

#define LSZ 64
#define SITES (LSZ * LSZ)      // 4096
#define NCH 6
#define RPW 8                  // rows per warp
#define NWARPS 8               // 8 warps -> 64 rows = whole batch
#define NTHREADS (NWARPS * 32) // 256

typedef unsigned long long u64;

__device__ __forceinline__ u64 pk2(float x, float y) {
    u64 r; asm("mov.b64 %0, {%1,%2};" : "=l"(r) : "f"(x), "f"(y)); return r;
}
__device__ __forceinline__ void upk2(u64 v, float& x, float& y) {
    asm("mov.b64 {%0,%1}, %2;" : "=f"(x), "=f"(y) : "l"(v));
}
__device__ __forceinline__ u64 fma2(u64 a, u64 b, u64 c) {
    u64 d; asm("fma.rn.f32x2 %0, %1, %2, %3;" : "=l"(d) : "l"(a), "l"(b), "l"(c)); return d;
}
__device__ __forceinline__ u64 mul2(u64 a, u64 b) {
    u64 d; asm("mul.rn.f32x2 %0, %1, %2;" : "=l"(d) : "l"(a), "l"(b)); return d;
}
__device__ __forceinline__ u64 sub2(u64 a, u64 b) {
    u64 d; asm("sub.rn.f32x2 %0, %1, %2;" : "=l"(d) : "l"(a), "l"(b)); return d;
}
__device__ __forceinline__ u64 add2(u64 a, u64 b) {
    u64 d; asm("add.rn.f32x2 %0, %1, %2;" : "=l"(d) : "l"(a), "l"(b)); return d;
}

// z-vector (7 comps) from 6 angles, no explicit range reduction
__device__ __forceinline__ void site_z(const float a[6], float z[7]) {
    float s[6], c[6];
    #pragma unroll
    for (int k = 0; k < 5; k++) {
        float sa = __sinf(a[k]);
        float ca = __cosf(a[k]);
        s[k] = fabsf(sa);
        c[k] = __uint_as_float(__float_as_uint(ca) ^
                               (__float_as_uint(sa) & 0x80000000u));
    }
    s[5] = __sinf(a[5]);
    c[5] = __cosf(a[5]);
    float sc = s[0];
    z[0] = c[0];
    z[1] = c[1] * sc; sc *= s[1];
    z[2] = c[2] * sc; sc *= s[2];
    z[3] = c[3] * sc; sc *= s[3];
    z[4] = c[4] * sc; sc *= s[4];   // zi0
    z[5] = c[5] * sc; sc *= s[5];   // zi1
    z[6] = sc;                      // zi2 (zi3 == 0 identically)
}

__device__ __forceinline__ void raw_to_z(float4 v0, float4 v1, float4 v2, u64 Z[7]) {
    float aA[6] = {v0.x, v0.y, v0.z, v0.w, v1.x, v1.y};
    float aB[6] = {v1.z, v1.w, v2.x, v2.y, v2.z, v2.w};
    float zA[7], zB[7];
    site_z(aA, zA);
    site_z(aB, zB);
    #pragma unroll
    for (int k = 0; k < 7; k++) Z[k] = pk2(zA[k], zB[k]);
}

// acc += dre^2 + dim^2, packed over 2 sites
__device__ __forceinline__ void accdot(const u64 S[7], const u64 N[7], u64& acc) {
    u64 pos = mul2(S[0], N[0]);
    pos = fma2(S[1], N[1], pos);
    pos = fma2(S[2], N[2], pos);
    pos = fma2(S[3], N[3], pos);
    u64 neg = mul2(S[4], N[4]);
    neg = fma2(S[5], N[5], neg);
    neg = fma2(S[6], N[6], neg);
    u64 dre = sub2(pos, neg);
    u64 dim = mul2(S[0], N[4]);
    dim = fma2(S[1], N[5], dim);
    dim = fma2(S[2], N[6], dim);
    dim = fma2(S[4], N[0], dim);
    dim = fma2(S[5], N[1], dim);
    dim = fma2(S[6], N[2], dim);
    acc = fma2(dre, dre, acc);
    acc = fma2(dim, dim, acc);
}

// column-direction dot: neighbor of pair (2l, 2l+1) is (2l+1, 2l+2)
__device__ __forceinline__ void coldot(const u64 S[7], int lane, u64& acc) {
    u64 C[7];
    #pragma unroll
    for (int k = 0; k < 7; k++) {
        float slo, shi;
        upk2(S[k], slo, shi);
        float nlo = __shfl_sync(0xffffffffu, slo, (lane + 1) & 31);
        C[k] = pk2(shi, nlo);
    }
    accdot(S, C, acc);
}

__global__ void __launch_bounds__(NTHREADS, 3)
cpn_main(const float* __restrict__ phi, float* __restrict__ out)
{
    const int b    = blockIdx.x;
    const int w    = threadIdx.x >> 5;
    const int lane = threadIdx.x & 31;
    const int r0   = w * RPW;                 // first owned row
    const float4* __restrict__ f4 =
        reinterpret_cast<const float4*>(phi + (size_t)b * SITES * NCH);
    const int lidx = 3 * lane;                // 96 float4 per row

    __shared__ u64 firstz[NWARPS][7][32];
    __shared__ float red[NWARPS];

    // first owned row -> S, publish for the warp above (row wrap included)
    u64 S[7];
    {
        int base = r0 * 96 + lidx;
        raw_to_z(f4[base], f4[base + 1], f4[base + 2], S);
    }
    #pragma unroll
    for (int k = 0; k < 7; k++) firstz[w][k][lane] = S[k];
    __syncthreads();

    u64 acc_a = pk2(0.0f, 0.0f);   // col dots
    u64 acc_b = pk2(0.0f, 0.0f);   // row dots

    // rows r0+1 .. r0+6 processed in pairs, two rows in flight
    #pragma unroll
    for (int r = 1; r + 1 < RPW; r += 2) {
        int base1 = (r0 + r) * 96 + lidx;
        int base2 = base1 + 96;
        // issue all 6 LDG.128 up front
        float4 a0 = f4[base1], a1 = f4[base1 + 1], a2 = f4[base1 + 2];
        float4 b0 = f4[base2], b1 = f4[base2 + 1], b2 = f4[base2 + 2];

        u64 R1[7], R2[7];
        raw_to_z(a0, a1, a2, R1);
        raw_to_z(b0, b1, b2, R2);   // independent of R1 chain

        coldot(S, lane, acc_a);
        accdot(S, R1, acc_b);
        coldot(R1, lane, acc_a);
        accdot(R1, R2, acc_b);
        #pragma unroll
        for (int k = 0; k < 7; k++) S[k] = R2[k];
    }

    // last owned row (r = RPW-1)
    {
        int base = (r0 + RPW - 1) * 96 + lidx;
        u64 R[7];
        raw_to_z(f4[base], f4[base + 1], f4[base + 2], R);
        coldot(S, lane, acc_a);
        accdot(S, R, acc_b);
        #pragma unroll
        for (int k = 0; k < 7; k++) S[k] = R[k];
    }

    // boundary: col dot + row dot vs next warp's first row (wraps 63->0)
    coldot(S, lane, acc_a);
    {
        u64 N[7];
        int nw = (w + 1) & (NWARPS - 1);
        #pragma unroll
        for (int k = 0; k < 7; k++) N[k] = firstz[nw][k][lane];
        accdot(S, N, acc_b);
    }

    // reduce: packed -> scalar -> warp -> block
    u64 acc2 = add2(acc_a, acc_b);
    float alo, ahi;
    upk2(acc2, alo, ahi);
    float acc = alo + ahi;
    #pragma unroll
    for (int o = 16; o > 0; o >>= 1)
        acc += __shfl_down_sync(0xffffffffu, acc, o);
    if (lane == 0) red[w] = acc;
    __syncthreads();
    if (threadIdx.x == 0) {
        float v = 0.0f;
        #pragma unroll
        for (int i = 0; i < NWARPS; i++) v += red[i];
        // action = -4 * sum(dre^2 + dim^2 - 1), 2 dirs * 4096 sites
        out[b] = -4.0f * (v - 2.0f * (float)SITES);
    }
}

extern "C" void kernel_launch(void* const* d_in, const int* in_sizes, int n_in,
                              void* d_out, int out_size)
{
    const float* phi = (const float*)d_in[0];
    // d_in[1] (shift) is the fixed (+1 row, +1 col) roll; handled analytically.
    int B = in_sizes[0] / (SITES * NCH);
    cpn_main<<<B, NTHREADS>>>(phi, (float*)d_out);
}